// round 6
// baseline (speedup 1.0000x reference)
#include <cuda_runtime.h>
#include <cstdint>
#include <cstddef>

#define NHEADS 12
#define HDIM   64
#define S_LEN  1024
#define BATCH  4
#define HID    768
#define BH     (BATCH * NHEADS)   // 48

// ---------------- scratch (__device__ globals; no allocation) ----------------
__device__ float g_Q[BH * S_LEN * HDIM];                 // 12.6 MB
__device__ float g_K[BH * S_LEN * HDIM];
__device__ float g_V[BH * S_LEN * HDIM];
__device__ float g_S[(size_t)BH * S_LEN * S_LEN];        // 201 MB scores/probs

// =============================================================================
// Kernel 1: fused QKV projection.  C[m][n] = sum_k X[m][k] * W[n][k] + bias[n]
// tile 128x128, K-tile 8, 256 threads, 8x8 microtile.
// Output written directly in [b, h, s, d] layout.
// =============================================================================
__global__ __launch_bounds__(256) void qkv_kernel(
    const float* __restrict__ X,
    const float* __restrict__ Wq, const float* __restrict__ bq,
    const float* __restrict__ Wk, const float* __restrict__ bk,
    const float* __restrict__ Wv, const float* __restrict__ bv)
{
    __shared__ float Xs[8 * 132];
    __shared__ float Ws[8 * 132];

    const float* W; const float* bias; float* out;
    int z = blockIdx.z;
    if (z == 0)      { W = Wq; bias = bq; out = g_Q; }
    else if (z == 1) { W = Wk; bias = bk; out = g_K; }
    else             { W = Wv; bias = bv; out = g_V; }

    int tid = threadIdx.x;
    int tx = tid & 15, ty = tid >> 4;
    int m0 = blockIdx.x * 128, n0 = blockIdx.y * 128;

    float acc[8][8];
    #pragma unroll
    for (int i = 0; i < 8; i++)
        #pragma unroll
        for (int j = 0; j < 8; j++) acc[i][j] = 0.f;

    int lrow = tid >> 1, lpart = tid & 1;

    for (int kt = 0; kt < HID; kt += 8) {
        float4 xv = *(const float4*)(X + (size_t)(m0 + lrow) * HID + kt + lpart * 4);
        float4 wv = *(const float4*)(W + (size_t)(n0 + lrow) * HID + kt + lpart * 4);
        __syncthreads();
        Xs[(lpart * 4 + 0) * 132 + lrow] = xv.x;
        Xs[(lpart * 4 + 1) * 132 + lrow] = xv.y;
        Xs[(lpart * 4 + 2) * 132 + lrow] = xv.z;
        Xs[(lpart * 4 + 3) * 132 + lrow] = xv.w;
        Ws[(lpart * 4 + 0) * 132 + lrow] = wv.x;
        Ws[(lpart * 4 + 1) * 132 + lrow] = wv.y;
        Ws[(lpart * 4 + 2) * 132 + lrow] = wv.z;
        Ws[(lpart * 4 + 3) * 132 + lrow] = wv.w;
        __syncthreads();
        #pragma unroll
        for (int kk = 0; kk < 8; kk++) {
            float a[8], b[8];
            #pragma unroll
            for (int i = 0; i < 8; i++) a[i] = Xs[kk * 132 + ty + 16 * i];
            #pragma unroll
            for (int j = 0; j < 8; j++) b[j] = Ws[kk * 132 + tx + 16 * j];
            #pragma unroll
            for (int i = 0; i < 8; i++)
                #pragma unroll
                for (int j = 0; j < 8; j++) acc[i][j] = fmaf(a[i], b[j], acc[i][j]);
        }
    }

    float bj[8];
    #pragma unroll
    for (int j = 0; j < 8; j++) bj[j] = bias[n0 + tx + 16 * j];

    #pragma unroll
    for (int i = 0; i < 8; i++) {
        int m = m0 + ty + 16 * i;
        int bb = m >> 10, s = m & 1023;
        #pragma unroll
        for (int j = 0; j < 8; j++) {
            int n = n0 + tx + 16 * j;
            int h = n >> 6, d = n & 63;
            out[(((size_t)(bb * NHEADS + h)) * S_LEN + s) * HDIM + d] = acc[i][j] + bj[j];
        }
    }
}

// =============================================================================
// Kernel 2: scores[l,r] = (q.k + q.D[t] + k.D[t]) / 8 + mask[b,r],
//           t = l - r + 1023.
// Per 64x64 (l,r) tile: load 128-row distance window Dw, compute
//   Cq = Q_tile @ Dw^T  and  Ck = K_tile @ Dw^T   (small GEMMs, in regs),
// stash them in smem, do the q.k GEMM, then gather the two bias diagonals.
// 256 threads, __launch_bounds__(256, 2): 2 CTAs/SM at 99.3 KB smem each.
// =============================================================================
__global__ __launch_bounds__(256, 2) void scores_kernel(
    const float* __restrict__ dist, const float* __restrict__ mask)
{
    extern __shared__ float sm[];
    float* Qs  = sm;            // 64 x 65  = 4160
    float* Ks  = sm + 4160;     // 64 x 65  = 4160
    float* Dw  = sm + 8320;     // 128 x 65 = 8320 (reused as CqS after phase B)
    float* CkS = sm + 16640;    // 64 x 128 = 8192
    float* CqS = Dw;            // 64 x 128 overlays Dw

    int tid = threadIdx.x;
    int tx = tid & 15, ty = tid >> 4;
    int bh = blockIdx.z, b = bh / NHEADS;
    int l0 = blockIdx.y << 6, r0 = blockIdx.x << 6;

    const float* Qp = g_Q + (size_t)bh * (S_LEN * HDIM);
    const float* Kp = g_K + (size_t)bh * (S_LEN * HDIM);

    for (int idx = tid; idx < 4096; idx += 256) {
        int l = idx >> 6, d = idx & 63;
        Qs[l * 65 + d] = Qp[(size_t)(l0 + l) * 64 + d];
        Ks[l * 65 + d] = Kp[(size_t)(r0 + l) * 64 + d];
    }
    int base = l0 - r0 + 960;   // window start: t = base + j, j in [0,127]
    for (int idx = tid; idx < 8192; idx += 256) {
        int j = idx >> 6, d = idx & 63;
        int t = base + j;
        Dw[j * 65 + d] = (t >= 0 && t < 2047) ? dist[(size_t)t * 64 + d] : 0.f;
    }
    __syncthreads();

    // Phase B: Cq[l][j] = sum_d Qs[l][d]*Dw[j][d];  Ck[r][j] likewise from Ks.
    float accq[4][8], acck[4][8];
    #pragma unroll
    for (int i = 0; i < 4; i++)
        #pragma unroll
        for (int j = 0; j < 8; j++) { accq[i][j] = 0.f; acck[i][j] = 0.f; }

    for (int d = 0; d < 64; d++) {
        float qa[4], ka[4], wb[8];
        #pragma unroll
        for (int i = 0; i < 4; i++) {
            qa[i] = Qs[(ty * 4 + i) * 65 + d];
            ka[i] = Ks[(ty * 4 + i) * 65 + d];
        }
        #pragma unroll
        for (int j = 0; j < 8; j++) wb[j] = Dw[(tx + (j << 4)) * 65 + d];
        #pragma unroll
        for (int i = 0; i < 4; i++)
            #pragma unroll
            for (int j = 0; j < 8; j++) {
                accq[i][j] = fmaf(qa[i], wb[j], accq[i][j]);
                acck[i][j] = fmaf(ka[i], wb[j], acck[i][j]);
            }
    }
    __syncthreads();   // everyone done reading Dw

    #pragma unroll
    for (int i = 0; i < 4; i++)
        #pragma unroll
        for (int j = 0; j < 8; j++) {
            CqS[(ty * 4 + i) * 128 + tx + (j << 4)] = accq[i][j];
            CkS[(ty * 4 + i) * 128 + tx + (j << 4)] = acck[i][j];
        }

    // Phase D: q.k 64x64 GEMM (reads only Qs/Ks; overlaps C-store latency)
    float acc[4][4];
    #pragma unroll
    for (int i = 0; i < 4; i++)
        #pragma unroll
        for (int r = 0; r < 4; r++) acc[i][r] = 0.f;

    for (int d = 0; d < 64; d++) {
        float qa[4], kb[4];
        #pragma unroll
        for (int i = 0; i < 4; i++) qa[i] = Qs[(ty * 4 + i) * 65 + d];
        #pragma unroll
        for (int r = 0; r < 4; r++) kb[r] = Ks[(tx + (r << 4)) * 65 + d];
        #pragma unroll
        for (int i = 0; i < 4; i++)
            #pragma unroll
            for (int r = 0; r < 4; r++) acc[i][r] = fmaf(qa[i], kb[r], acc[i][r]);
    }
    __syncthreads();   // CqS/CkS visible

    const float* mrow = mask + b * S_LEN + r0;
    #pragma unroll
    for (int i = 0; i < 4; i++) {
        int li = ty * 4 + i;
        float* outp = g_S + ((size_t)bh * S_LEN + (l0 + li)) * S_LEN + r0;
        #pragma unroll
        for (int r = 0; r < 4; r++) {
            int ri = tx + (r << 4);
            int j = li - ri + 63;                       // in [0,126]
            float sv = (acc[i][r] + CqS[li * 128 + j] + CkS[ri * 128 + j]) * 0.125f
                     + mrow[ri];
            outp[ri] = sv;
        }
    }
}

// =============================================================================
// Kernel 3: row softmax, in place.  Polynomial exp2 on the FMA pipe —
// avoids the ~340us MUFU.EX2 throughput wall (rt_SMSP=8).
// One warp per row, 4 rows per 128-thread block.
// =============================================================================
__device__ __forceinline__ float fast_exp(float x)
{
    float y = x * 1.4426950408889634f;       // x * log2(e)
    y = fmaxf(y, -120.f);
    float r = rintf(y);
    float f = y - r;                          // |f| <= 0.5
    float z = f * 0.6931471805599453f;        // |z| <= 0.3466
    float p = fmaf(z, 0.008333333f, 0.041666668f);
    p = fmaf(z, p, 0.16666667f);
    p = fmaf(z, p, 0.5f);
    p = fmaf(z, p, 1.0f);
    p = fmaf(z, p, 1.0f);
    int e = (int)r;
    float s = __int_as_float((e + 127) << 23);
    return s * p;
}

__global__ __launch_bounds__(128) void softmax_kernel()
{
    int warp = threadIdx.x >> 5, lane = threadIdx.x & 31;
    size_t row = (size_t)blockIdx.x * 4 + warp;
    float* p = g_S + row * S_LEN;

    float x[32];
    #pragma unroll
    for (int i = 0; i < 32; i++) x[i] = p[lane + (i << 5)];

    float m = x[0];
    #pragma unroll
    for (int i = 1; i < 32; i++) m = fmaxf(m, x[i]);
    #pragma unroll
    for (int o = 16; o; o >>= 1) m = fmaxf(m, __shfl_xor_sync(0xffffffffu, m, o));

    float sum = 0.f;
    #pragma unroll
    for (int i = 0; i < 32; i++) { x[i] = fast_exp(x[i] - m); sum += x[i]; }
    #pragma unroll
    for (int o = 16; o; o >>= 1) sum += __shfl_xor_sync(0xffffffffu, sum, o);

    float inv = 1.0f / sum;
    #pragma unroll
    for (int i = 0; i < 32; i++) p[lane + (i << 5)] = x[i] * inv;
}

// =============================================================================
// Kernel 4: ctx = P @ V, written straight to [B,S,H] output layout.
// tile 64 l x 64 d, K-tile 32, 256 threads, 4x4 microtile.
// =============================================================================
__global__ __launch_bounds__(256) void pv_kernel(float* __restrict__ out)
{
    __shared__ float Ps[64 * 33];
    __shared__ float Vs[32 * 64];

    int tid = threadIdx.x;
    int tx = tid & 15, ty = tid >> 4;
    int bh = blockIdx.y, l0 = blockIdx.x << 6;
    int b = bh / NHEADS, h = bh % NHEADS;

    const float* Pp = g_S + ((size_t)bh * S_LEN + l0) * S_LEN;
    const float* Vp = g_V + (size_t)bh * (S_LEN * HDIM);

    float acc[4][4];
    #pragma unroll
    for (int i = 0; i < 4; i++)
        #pragma unroll
        for (int j = 0; j < 4; j++) acc[i][j] = 0.f;

    for (int kt = 0; kt < S_LEN; kt += 32) {
        __syncthreads();
        for (int idx = tid; idx < 2048; idx += 256) {
            int l = idx >> 5, kk = idx & 31;
            Ps[l * 33 + kk] = Pp[(size_t)l * S_LEN + kt + kk];
        }
        for (int idx = tid; idx < 2048; idx += 256) {
            int kk = idx >> 6, d = idx & 63;
            Vs[kk * 64 + d] = Vp[(size_t)(kt + kk) * 64 + d];
        }
        __syncthreads();
        #pragma unroll
        for (int kk = 0; kk < 32; kk++) {
            float a[4], bb[4];
            #pragma unroll
            for (int i = 0; i < 4; i++) a[i] = Ps[(ty * 4 + i) * 33 + kk];
            #pragma unroll
            for (int j = 0; j < 4; j++) bb[j] = Vs[kk * 64 + tx + (j << 4)];
            #pragma unroll
            for (int i = 0; i < 4; i++)
                #pragma unroll
                for (int j = 0; j < 4; j++) acc[i][j] = fmaf(a[i], bb[j], acc[i][j]);
        }
    }

    #pragma unroll
    for (int i = 0; i < 4; i++)
        #pragma unroll
        for (int j = 0; j < 4; j++)
            out[((size_t)b * S_LEN + l0 + ty * 4 + i) * HID + h * HDIM + tx + (j << 4)]
                = acc[i][j];
}

// =============================================================================
extern "C" void kernel_launch(void* const* d_in, const int* in_sizes, int n_in,
                              void* d_out, int out_size)
{
    const float* hidden = (const float*)d_in[0];
    const float* mask   = (const float*)d_in[1];
    const float* Wq     = (const float*)d_in[2];
    const float* bq     = (const float*)d_in[3];
    const float* Wk     = (const float*)d_in[4];
    const float* bk     = (const float*)d_in[5];
    const float* Wv     = (const float*)d_in[6];
    const float* bv     = (const float*)d_in[7];
    const float* dist   = (const float*)d_in[8];
    float* out          = (float*)d_out;

    qkv_kernel<<<dim3(32, 6, 3), 256>>>(hidden, Wq, bq, Wk, bk, Wv, bv);

    static const int SCORES_SMEM = 24832 * 4;   // 99328 B
    cudaFuncSetAttribute(scores_kernel,
                         cudaFuncAttributeMaxDynamicSharedMemorySize, SCORES_SMEM);
    scores_kernel<<<dim3(16, 16, 48), 256, SCORES_SMEM>>>(dist, mask);

    softmax_kernel<<<(BH * S_LEN) / 4, 128>>>();

    pv_kernel<<<dim3(16, 48), 256>>>(out);
}

// round 10
// speedup vs baseline: 1.6292x; 1.6292x over previous
#include <cuda_runtime.h>
#include <cuda_fp16.h>
#include <cstdint>
#include <cstddef>

#define NHEADS 12
#define HDIM   64
#define S_LEN  1024
#define BATCH  4
#define HID    768
#define BH     (BATCH * NHEADS)   // 48
#define DROWS  2048

// ---------------- scratch (__device__ globals; no allocation) ----------------
__device__ __half g_Qh[BH * S_LEN * HDIM];
__device__ __half g_Ql[BH * S_LEN * HDIM];
__device__ __half g_Kh[BH * S_LEN * HDIM];
__device__ float  g_V [BH * S_LEN * HDIM];
__device__ __half g_VTh[BH * HDIM * S_LEN];            // [bh][d][s] fp16 hi
__device__ __half g_VTl[BH * HDIM * S_LEN];            // [bh][d][s] fp16 lo
__device__ __half g_Dh[DROWS * HDIM];                  // padded dist fp16
__device__ float  g_S[(size_t)BH * S_LEN * S_LEN];     // scores fp32
__device__ __half g_Ph[(size_t)BH * S_LEN * S_LEN];    // probs fp16 hi
__device__ __half g_Pl[(size_t)BH * S_LEN * S_LEN];    // probs fp16 lo

// ===================== mma.sync helpers (portable sm_80+) ====================
__device__ __forceinline__ uint32_t smem_u32(const void* p) {
    uint32_t a;
    asm("{ .reg .u64 t; cvta.to.shared.u64 t, %1; cvt.u32.u64 %0, t; }"
        : "=r"(a) : "l"(p));
    return a;
}
__device__ __forceinline__ void ldsm_x4(uint32_t r[4], uint32_t addr) {
    asm volatile("ldmatrix.sync.aligned.m8n8.x4.shared.b16 {%0,%1,%2,%3}, [%4];"
                 : "=r"(r[0]), "=r"(r[1]), "=r"(r[2]), "=r"(r[3]) : "r"(addr));
}
__device__ __forceinline__ void mma16816(float* c, const uint32_t a[4],
                                         uint32_t b0, uint32_t b1) {
    asm volatile("mma.sync.aligned.m16n8k16.row.col.f32.f16.f16.f32 "
                 "{%0,%1,%2,%3}, {%4,%5,%6,%7}, {%8,%9}, {%0,%1,%2,%3};"
                 : "+f"(c[0]), "+f"(c[1]), "+f"(c[2]), "+f"(c[3])
                 : "r"(a[0]), "r"(a[1]), "r"(a[2]), "r"(a[3]), "r"(b0), "r"(b1));
}

#define LDT 72   // smem tile stride in halfs (144 B: conflict-free ldmatrix)

// Warp-level GEMM: C[32 x NT*8] += A[32 x 64] * B[NT*8 x 64]^T
// A row-major [m][k], B row-major [n][k] (== col-major KxN), both stride LDT.
// B fragments via NON-trans ldmatrix: [n][k] storage is already the col-major
// layout mma wants (thread t gets M[n=t/4][k=2(t%4)] = b-fragment exactly).
template<int NT>
__device__ __forceinline__ void wgemm_k64(const __half* As, const __half* Bs,
                                          float* acc, int lane)
{
    #pragma unroll
    for (int k = 0; k < 4; k++) {
        uint32_t a[2][4];
        #pragma unroll
        for (int m = 0; m < 2; m++) {
            uint32_t addr = smem_u32(As + (m * 16 + (lane & 15)) * LDT
                                        + k * 16 + ((lane >> 4) << 3));
            ldsm_x4(a[m], addr);
        }
        uint32_t b[NT][2];
        #pragma unroll
        for (int np = 0; np < NT / 2; np++) {
            uint32_t r[4];
            // lanes 0-7: n 0-7,k0 | 8-15: n 0-7,k8 | 16-23: n 8-15,k0 | 24-31: n 8-15,k8
            uint32_t addr = smem_u32(Bs + (np * 16 + (lane & 7) + ((lane >> 4) << 3)) * LDT
                                        + k * 16 + (((lane >> 3) & 1) << 3));
            ldsm_x4(r, addr);
            b[2*np][0] = r[0]; b[2*np][1] = r[1];
            b[2*np+1][0] = r[2]; b[2*np+1][1] = r[3];
        }
        #pragma unroll
        for (int m = 0; m < 2; m++)
            #pragma unroll
            for (int n = 0; n < NT; n++)
                mma16816(acc + (m * NT + n) * 4, a[m], b[n][0], b[n][1]);
    }
}

// copy [rows x 64] fp16 tile (src row stride rs halfs) into smem, stride LDT
__device__ __forceinline__ void ldtile16(__half* dst, const __half* src,
                                         int rows, int rs, int tid, int nthr) {
    for (int idx = tid; idx < rows * 8; idx += nthr) {
        int r = idx >> 3, v = idx & 7;
        uint4 x = *(const uint4*)(src + (size_t)r * rs + v * 8);
        *(uint4*)(dst + r * LDT + v * 8) = x;
    }
}

// =============================================================================
// Kernel 1: fused QKV projection (fp32 FMA).
// Q -> fp16 hi/lo; K -> fp16; V -> fp32 (transposed later).
// =============================================================================
__global__ __launch_bounds__(256) void qkv_kernel(
    const float* __restrict__ X,
    const float* __restrict__ Wq, const float* __restrict__ bq,
    const float* __restrict__ Wk, const float* __restrict__ bk,
    const float* __restrict__ Wv, const float* __restrict__ bv)
{
    __shared__ float Xs[8 * 132];
    __shared__ float Ws[8 * 132];

    const float* W; const float* bias;
    int z = blockIdx.z;
    if (z == 0)      { W = Wq; bias = bq; }
    else if (z == 1) { W = Wk; bias = bk; }
    else             { W = Wv; bias = bv; }

    int tid = threadIdx.x;
    int tx = tid & 15, ty = tid >> 4;
    int m0 = blockIdx.x * 128, n0 = blockIdx.y * 128;

    float acc[8][8];
    #pragma unroll
    for (int i = 0; i < 8; i++)
        #pragma unroll
        for (int j = 0; j < 8; j++) acc[i][j] = 0.f;

    int lrow = tid >> 1, lpart = tid & 1;

    for (int kt = 0; kt < HID; kt += 8) {
        float4 xv = *(const float4*)(X + (size_t)(m0 + lrow) * HID + kt + lpart * 4);
        float4 wv = *(const float4*)(W + (size_t)(n0 + lrow) * HID + kt + lpart * 4);
        __syncthreads();
        Xs[(lpart * 4 + 0) * 132 + lrow] = xv.x;
        Xs[(lpart * 4 + 1) * 132 + lrow] = xv.y;
        Xs[(lpart * 4 + 2) * 132 + lrow] = xv.z;
        Xs[(lpart * 4 + 3) * 132 + lrow] = xv.w;
        Ws[(lpart * 4 + 0) * 132 + lrow] = wv.x;
        Ws[(lpart * 4 + 1) * 132 + lrow] = wv.y;
        Ws[(lpart * 4 + 2) * 132 + lrow] = wv.z;
        Ws[(lpart * 4 + 3) * 132 + lrow] = wv.w;
        __syncthreads();
        #pragma unroll
        for (int kk = 0; kk < 8; kk++) {
            float a[8], b[8];
            #pragma unroll
            for (int i = 0; i < 8; i++) a[i] = Xs[kk * 132 + ty + 16 * i];
            #pragma unroll
            for (int j = 0; j < 8; j++) b[j] = Ws[kk * 132 + tx + 16 * j];
            #pragma unroll
            for (int i = 0; i < 8; i++)
                #pragma unroll
                for (int j = 0; j < 8; j++) acc[i][j] = fmaf(a[i], b[j], acc[i][j]);
        }
    }

    float bj[8];
    #pragma unroll
    for (int j = 0; j < 8; j++) bj[j] = bias[n0 + tx + 16 * j];

    #pragma unroll
    for (int i = 0; i < 8; i++) {
        int m = m0 + ty + 16 * i;
        int bb = m >> 10, s = m & 1023;
        #pragma unroll
        for (int j = 0; j < 8; j++) {
            int n = n0 + tx + 16 * j;
            int h = n >> 6, d = n & 63;
            size_t idx = (((size_t)(bb * NHEADS + h)) * S_LEN + s) * HDIM + d;
            float val = acc[i][j] + bj[j];
            if (z == 2) {
                g_V[idx] = val;
            } else if (z == 1) {
                g_Kh[idx] = __float2half(val);
            } else {
                __half hv = __float2half(val);
                g_Qh[idx] = hv;
                g_Ql[idx] = __float2half(val - __half2float(hv));
            }
        }
    }
}

// =============================================================================
// Kernel 1b: pad + convert dist embedding to fp16 (rows >= 2047 -> 0)
// =============================================================================
__global__ __launch_bounds__(256) void prep_dist_kernel(const float* __restrict__ dist)
{
    int idx = blockIdx.x * 256 + threadIdx.x;
    int t = idx >> 6;
    float v = (t < 2047) ? dist[idx] : 0.f;
    g_Dh[idx] = __float2half(v);
}

// =============================================================================
// Kernel 1c: V transpose [bh][s][d] f32 -> [bh][d][s] fp16 hi/lo
// =============================================================================
__global__ __launch_bounds__(256) void vt_kernel()
{
    __shared__ float st[64 * 65];
    int bh = blockIdx.y, s0 = blockIdx.x << 6;
    const float* Vp = g_V + (size_t)bh * (S_LEN * HDIM);
    for (int idx = threadIdx.x; idx < 4096; idx += 256) {
        int sl = idx >> 6, d = idx & 63;
        st[d * 65 + sl] = Vp[(size_t)(s0 + sl) * 64 + d];
    }
    __syncthreads();
    for (int idx = threadIdx.x; idx < 4096; idx += 256) {
        int d = idx >> 6, sl = idx & 63;
        float v = st[d * 65 + sl];
        __half hv = __float2half(v);
        size_t o = ((size_t)bh * 64 + d) * S_LEN + s0 + sl;
        g_VTh[o] = hv;
        g_VTl[o] = __float2half(v - __half2float(hv));
    }
}

// =============================================================================
// Kernel 2: scores via mma.sync.  One 128x128 (l,r) tile per CTA, 8 warps.
//   window j = l_loc - r_loc + 127 in [0,254];  D row = t0 + j, t0 = l0-r0+896
//   phases: Cq = Qh·Dw^T (2 halves) -> CqS ; Ck = Kh·Dw^T -> CkS ;
//           QK = Qh·Kh^T + Ql·Kh^T (regs)
//   epilogue: (QK + CqS[l][j] + CkS[r][j]) * 0.125 + mask[r] -> g_S (float2)
// smem (halfs): Qh 0 | Ql 9216 | Kh 18432 | Dw 27648 (256xLDT)
//               CqS 46080 (128x264) | CkS 79872 | mask f32 @byte 227328
// total 227840 B
// =============================================================================
#define CQS_LD 264
#define SC_SMEM 227840
__global__ __launch_bounds__(256) void scores_mma_kernel(const float* __restrict__ mask)
{
    extern __shared__ __half sh[];
    __half* Qh  = sh;
    __half* Ql  = sh + 9216;
    __half* Kh  = sh + 18432;
    __half* Dw  = sh + 27648;
    __half* CqS = sh + 46080;
    __half* CkS = sh + 79872;
    float*  mask_s = (float*)((char*)sh + 227328);

    int tid = threadIdx.x, wid = tid >> 5, lane = tid & 31;
    int wm = wid >> 1, wn = wid & 1;           // 4 x 2 warp grid

    int bh = blockIdx.z, b = bh / NHEADS;
    int l0 = blockIdx.y << 7, r0 = blockIdx.x << 7;
    int t0 = l0 - r0 + 896;

    size_t qoff = (size_t)bh * (S_LEN * HDIM) + (size_t)l0 * 64;
    size_t koff = (size_t)bh * (S_LEN * HDIM) + (size_t)r0 * 64;
    ldtile16(Qh, g_Qh + qoff, 128, 64, tid, 256);
    ldtile16(Ql, g_Ql + qoff, 128, 64, tid, 256);
    ldtile16(Kh, g_Kh + koff, 128, 64, tid, 256);
    ldtile16(Dw, g_Dh + (size_t)t0 * 64, 256, 64, tid, 256);
    if (tid < 128) mask_s[tid] = mask[b * S_LEN + r0 + tid];
    __syncthreads();

    // ---- bias phases: Cq then Ck, each over two 128-col window halves ----
    #pragma unroll
    for (int side = 0; side < 2; side++) {
        const __half* A = (side == 0 ? Qh : Kh) + wm * 32 * LDT;
        __half* Cdst = (side == 0 ? CqS : CkS);
        #pragma unroll
        for (int h = 0; h < 2; h++) {
            float acc[64];
            #pragma unroll
            for (int i = 0; i < 64; i++) acc[i] = 0.f;
            wgemm_k64<8>(A, Dw + (h * 128 + wn * 64) * LDT, acc, lane);
            #pragma unroll
            for (int m = 0; m < 2; m++)
                #pragma unroll
                for (int n = 0; n < 8; n++) {
                    float* c = acc + (m * 8 + n) * 4;
                    int row = wm * 32 + m * 16 + (lane >> 2);
                    int col = h * 128 + wn * 64 + n * 8 + ((lane & 3) << 1);
                    *(half2*)(Cdst + row * CQS_LD + col) =
                        __floats2half2_rn(c[0], c[1]);
                    *(half2*)(Cdst + (row + 8) * CQS_LD + col) =
                        __floats2half2_rn(c[2], c[3]);
                }
        }
    }

    // ---- QK phase: Qh·Kh^T + Ql·Kh^T ----
    float acc[64];
    #pragma unroll
    for (int i = 0; i < 64; i++) acc[i] = 0.f;
    wgemm_k64<8>(Qh + wm * 32 * LDT, Kh + wn * 64 * LDT, acc, lane);
    wgemm_k64<8>(Ql + wm * 32 * LDT, Kh + wn * 64 * LDT, acc, lane);
    __syncthreads();   // CqS / CkS complete

    // ---- epilogue ----
    #pragma unroll
    for (int m = 0; m < 2; m++)
        #pragma unroll
        for (int n = 0; n < 8; n++) {
            float* c = acc + (m * 8 + n) * 4;
            int lrow = wm * 32 + m * 16 + (lane >> 2);
            int rr   = wn * 64 + n * 8 + ((lane & 3) << 1);
            #pragma unroll
            for (int half_i = 0; half_i < 2; half_i++) {
                int l_loc = lrow + half_i * 8;
                int j0 = l_loc - rr + 127;
                float s0 = (c[half_i * 2 + 0]
                            + __half2float(CqS[l_loc * CQS_LD + j0])
                            + __half2float(CkS[rr * CQS_LD + j0])) * 0.125f
                           + mask_s[rr];
                float s1 = (c[half_i * 2 + 1]
                            + __half2float(CqS[l_loc * CQS_LD + j0 - 1])
                            + __half2float(CkS[(rr + 1) * CQS_LD + j0 - 1])) * 0.125f
                           + mask_s[rr + 1];
                float2 v = make_float2(s0, s1);
                *(float2*)(g_S + ((size_t)bh * S_LEN + l0 + l_loc) * S_LEN + r0 + rr) = v;
            }
        }
}

// =============================================================================
// Kernel 3: row softmax (fp32 in, fp16 hi/lo probs out). FMA-pipe exp.
// =============================================================================
__device__ __forceinline__ float fast_exp(float x)
{
    float y = x * 1.4426950408889634f;
    y = fmaxf(y, -120.f);
    float r = rintf(y);
    float f = y - r;
    float z = f * 0.6931471805599453f;
    float p = fmaf(z, 0.008333333f, 0.041666668f);
    p = fmaf(z, p, 0.16666667f);
    p = fmaf(z, p, 0.5f);
    p = fmaf(z, p, 1.0f);
    p = fmaf(z, p, 1.0f);
    int e = (int)r;
    float s = __int_as_float((e + 127) << 23);
    return s * p;
}

__global__ __launch_bounds__(128) void softmax_kernel()
{
    int warp = threadIdx.x >> 5, lane = threadIdx.x & 31;
    size_t rowi = (size_t)blockIdx.x * 4 + warp;
    const float* p = g_S + rowi * S_LEN;
    __half* ph = g_Ph + rowi * S_LEN;
    __half* pl = g_Pl + rowi * S_LEN;

    float x[32];
    #pragma unroll
    for (int i = 0; i < 32; i++) x[i] = p[lane + (i << 5)];

    float m = x[0];
    #pragma unroll
    for (int i = 1; i < 32; i++) m = fmaxf(m, x[i]);
    #pragma unroll
    for (int o = 16; o; o >>= 1) m = fmaxf(m, __shfl_xor_sync(0xffffffffu, m, o));

    float sum = 0.f;
    #pragma unroll
    for (int i = 0; i < 32; i++) { x[i] = fast_exp(x[i] - m); sum += x[i]; }
    #pragma unroll
    for (int o = 16; o; o >>= 1) sum += __shfl_xor_sync(0xffffffffu, sum, o);

    float inv = 1.0f / sum;
    #pragma unroll
    for (int i = 0; i < 32; i++) {
        float v = x[i] * inv;
        __half hv = __float2half(v);
        int idx = lane + (i << 5);
        ph[idx] = hv;
        pl[idx] = __float2half(v - __half2float(hv));
    }
}

// =============================================================================
// Kernel 4: ctx = P @ V, 3-term compensated (Ph·Vh + Pl·Vh + Ph·Vl).
// 128(l) x 64(d) per CTA, K=1024 in 16 chunks. 8 warps (4x2), 32x32 each.
// smem halfs: Pth 0 | Ptl 9216 | Vth 18432 | Vtl 23040 ; total 55296 B
// =============================================================================
#define PV_SMEM 55296
__global__ __launch_bounds__(256) void pv_mma_kernel(float* __restrict__ out)
{
    extern __shared__ __half sh[];
    __half* Pth = sh;
    __half* Ptl = sh + 9216;
    __half* Vth = sh + 18432;
    __half* Vtl = sh + 23040;

    int tid = threadIdx.x, wid = tid >> 5, lane = tid & 31;
    int wm = wid >> 1, wn = wid & 1;
    int bh = blockIdx.y, l0 = blockIdx.x << 7;
    int b = bh / NHEADS, h = bh % NHEADS;

    const __half* Php = g_Ph + ((size_t)bh * S_LEN + l0) * S_LEN;
    const __half* Plp = g_Pl + ((size_t)bh * S_LEN + l0) * S_LEN;
    const __half* Vhp = g_VTh + (size_t)bh * (HDIM * S_LEN);
    const __half* Vlp = g_VTl + (size_t)bh * (HDIM * S_LEN);

    float acc[32];
    #pragma unroll
    for (int i = 0; i < 32; i++) acc[i] = 0.f;

    for (int kt = 0; kt < S_LEN; kt += 64) {
        __syncthreads();
        ldtile16(Pth, Php + kt, 128, S_LEN, tid, 256);
        ldtile16(Ptl, Plp + kt, 128, S_LEN, tid, 256);
        ldtile16(Vth, Vhp + kt,  64, S_LEN, tid, 256);
        ldtile16(Vtl, Vlp + kt,  64, S_LEN, tid, 256);
        __syncthreads();
        wgemm_k64<4>(Pth + wm * 32 * LDT, Vth + wn * 32 * LDT, acc, lane);
        wgemm_k64<4>(Ptl + wm * 32 * LDT, Vth + wn * 32 * LDT, acc, lane);
        wgemm_k64<4>(Pth + wm * 32 * LDT, Vtl + wn * 32 * LDT, acc, lane);
    }

    #pragma unroll
    for (int m = 0; m < 2; m++)
        #pragma unroll
        for (int n = 0; n < 4; n++) {
            float* c = acc + (m * 4 + n) * 4;
            int lrow = wm * 32 + m * 16 + (lane >> 2);
            int d    = wn * 32 + n * 8 + ((lane & 3) << 1);
            float* o0 = out + ((size_t)b * S_LEN + l0 + lrow) * HID + h * HDIM + d;
            *(float2*)o0 = make_float2(c[0], c[1]);
            float* o1 = o0 + 8 * HID;
            *(float2*)o1 = make_float2(c[2], c[3]);
        }
}

// =============================================================================
extern "C" void kernel_launch(void* const* d_in, const int* in_sizes, int n_in,
                              void* d_out, int out_size)
{
    const float* hidden = (const float*)d_in[0];
    const float* mask   = (const float*)d_in[1];
    const float* Wq     = (const float*)d_in[2];
    const float* bq     = (const float*)d_in[3];
    const float* Wk     = (const float*)d_in[4];
    const float* bk     = (const float*)d_in[5];
    const float* Wv     = (const float*)d_in[6];
    const float* bv     = (const float*)d_in[7];
    const float* dist   = (const float*)d_in[8];
    float* out          = (float*)d_out;

    cudaFuncSetAttribute(scores_mma_kernel,
                         cudaFuncAttributeMaxDynamicSharedMemorySize, SC_SMEM);
    cudaFuncSetAttribute(pv_mma_kernel,
                         cudaFuncAttributeMaxDynamicSharedMemorySize, PV_SMEM);

    qkv_kernel<<<dim3(32, 6, 3), 256>>>(hidden, Wq, bq, Wk, bk, Wv, bv);
    prep_dist_kernel<<<(DROWS * 64) / 256, 256>>>(dist);
    vt_kernel<<<dim3(16, BH), 256>>>();
    scores_mma_kernel<<<dim3(8, 8, BH), 256, SC_SMEM>>>(mask);
    softmax_kernel<<<(BH * S_LEN) / 4, 128>>>();
    pv_mma_kernel<<<dim3(8, BH), 256, PV_SMEM>>>(out);
}